// round 1
// baseline (speedup 1.0000x reference)
#include <cuda_runtime.h>
#include <math.h>

#define BATCH 8
#define SEQ 1024
#define DIM 1024
#define NH 16
#define HS 64
#define TOK (BATCH*SEQ)   // 8192
#define FFD (4*DIM)       // 4096
#define D3  (3*DIM)       // 3072

// ---------------- scratch (device globals; no allocation allowed) ----------
__device__ float g_h[TOK*DIM];          // LN output (reused)
__device__ float g_qkv[TOK*D3];         // fused q|k|v  [token][3072]
__device__ float g_attn[TOK*DIM];       // attention out, [B,N,H*HS]
__device__ float g_x1[TOK*DIM];         // x + attn@Wproj
__device__ float g_ff[(size_t)TOK*FFD]; // FF intermediate
__device__ float g_wqkv[DIM*D3];        // packed [d][h*64+s | +1024 | +2048]
__device__ float g_bqkv[D3];

// ---------------- pack per-head weights into one [D, 3D] matrix ------------
__global__ void pack_qkv(const float* __restrict__ Wq, const float* __restrict__ Wk,
                         const float* __restrict__ Wv, const float* __restrict__ bq,
                         const float* __restrict__ bk, const float* __restrict__ bv) {
    int i = blockIdx.x * blockDim.x + threadIdx.x;
    if (i < NH * DIM * HS) {
        int h = i >> 16;            // i / (DIM*HS)
        int rem = i & 65535;
        int d = rem >> 6;
        int s = rem & 63;
        int dst = d * D3 + h * HS + s;
        g_wqkv[dst]         = Wq[i];
        g_wqkv[dst + DIM]   = Wk[i];
        g_wqkv[dst + 2*DIM] = Wv[i];
    }
    if (i < DIM) {
        g_bqkv[i]         = bq[i];
        g_bqkv[i + DIM]   = bk[i];
        g_bqkv[i + 2*DIM] = bv[i];
    }
}

// ---------------- layernorm: one block (256 thr) per row of 1024 -----------
__global__ void ln_kernel(const float* __restrict__ x, const float* __restrict__ g,
                          const float* __restrict__ b, float* __restrict__ out) {
    int row = blockIdx.x;
    const float4* xr = (const float4*)(x + (size_t)row * DIM);
    float4 v = xr[threadIdx.x];
    float s  = v.x + v.y + v.z + v.w;
    float ss = v.x*v.x + v.y*v.y + v.z*v.z + v.w*v.w;
    #pragma unroll
    for (int o = 16; o; o >>= 1) {
        s  += __shfl_xor_sync(0xFFFFFFFFu, s, o);
        ss += __shfl_xor_sync(0xFFFFFFFFu, ss, o);
    }
    __shared__ float sm[8], sm2[8];
    int w = threadIdx.x >> 5, l = threadIdx.x & 31;
    if (l == 0) { sm[w] = s; sm2[w] = ss; }
    __syncthreads();
    if (w == 0) {
        s  = (l < 8) ? sm[l]  : 0.f;
        ss = (l < 8) ? sm2[l] : 0.f;
        #pragma unroll
        for (int o = 4; o; o >>= 1) {
            s  += __shfl_xor_sync(0xFFFFFFFFu, s, o);
            ss += __shfl_xor_sync(0xFFFFFFFFu, ss, o);
        }
        if (l == 0) { sm[0] = s; sm2[0] = ss; }
    }
    __syncthreads();
    float mu   = sm[0] * (1.0f / DIM);
    float var  = sm2[0] * (1.0f / DIM) - mu * mu;
    float rstd = rsqrtf(var + 1e-5f);
    float4 gg = ((const float4*)g)[threadIdx.x];
    float4 bb = ((const float4*)b)[threadIdx.x];
    float4 o4;
    o4.x = (v.x - mu) * rstd * gg.x + bb.x;
    o4.y = (v.y - mu) * rstd * gg.y + bb.y;
    o4.z = (v.z - mu) * rstd * gg.z + bb.z;
    o4.w = (v.w - mu) * rstd * gg.w + bb.w;
    ((float4*)(out + (size_t)row * DIM))[threadIdx.x] = o4;
}

// ---------------- generic sgemm 128x128x16, 8x8 microtile ------------------
// C[M,N] = epi(A[M,K] @ Bm[K,N] + bias[N]) (+ res[M,N])
template<bool LEAKY, bool RES>
__global__ __launch_bounds__(256)
void sgemm(const float* __restrict__ A, const float* __restrict__ Bm,
           const float* __restrict__ bias, const float* __restrict__ res,
           float* __restrict__ C, int M, int N, int K) {
    __shared__ float As[16][128];
    __shared__ float Bs[16][128];
    int tid = threadIdx.x;
    int bm = blockIdx.y, bn = blockIdx.x;
    int tr = tid >> 4, tc = tid & 15;
    float acc[8][8] = {};
    const float* Ab = A + (size_t)bm * 128 * K;
    const float* Bb = Bm + bn * 128;
    for (int k0 = 0; k0 < K; k0 += 16) {
        #pragma unroll
        for (int t = 0; t < 2; t++) {
            int lid = tid + t * 256;
            int ar = lid >> 2, ac = (lid & 3) * 4;
            float4 av = *(const float4*)(Ab + (size_t)ar * K + k0 + ac);
            As[ac + 0][ar] = av.x; As[ac + 1][ar] = av.y;
            As[ac + 2][ar] = av.z; As[ac + 3][ar] = av.w;
        }
        #pragma unroll
        for (int t = 0; t < 2; t++) {
            int lid = tid + t * 256;
            int br = lid >> 5, bc = (lid & 31) * 4;
            *(float4*)(&Bs[br][bc]) = *(const float4*)(Bb + (size_t)(k0 + br) * N + bc);
        }
        __syncthreads();
        #pragma unroll
        for (int kk = 0; kk < 16; kk++) {
            float a[8], bv[8];
            *(float4*)(a)     = *(const float4*)(&As[kk][tr * 8]);
            *(float4*)(a + 4) = *(const float4*)(&As[kk][tr * 8 + 4]);
            *(float4*)(bv)     = *(const float4*)(&Bs[kk][tc * 8]);
            *(float4*)(bv + 4) = *(const float4*)(&Bs[kk][tc * 8 + 4]);
            #pragma unroll
            for (int i = 0; i < 8; i++)
                #pragma unroll
                for (int j = 0; j < 8; j++)
                    acc[i][j] += a[i] * bv[j];
        }
        __syncthreads();
    }
    #pragma unroll
    for (int i = 0; i < 8; i++) {
        int row = bm * 128 + tr * 8 + i;
        #pragma unroll
        for (int j = 0; j < 8; j++) {
            int col = bn * 128 + tc * 8 + j;
            float c = acc[i][j] + bias[col];
            if (LEAKY) c = c > 0.f ? c : 0.01f * c;
            if (RES)   c += res[(size_t)row * N + col];
            C[(size_t)row * N + col] = c;
        }
    }
}

// ---------------- flash attention: 64 q-rows per block, 64-key tiles -------
// q/k/v live in g_qkv: token t, head h -> q at [t*3072 + h*64], k +1024, v +2048
__global__ __launch_bounds__(256)
void flash_attn(const float* __restrict__ qkv, float* __restrict__ attn_out) {
    extern __shared__ float smem[];
    float (*Qs)[65] = (float(*)[65])smem;
    float (*Ks)[65] = (float(*)[65])(smem + 64 * 65);
    float (*Vs)[65] = (float(*)[65])(smem + 2 * 64 * 65);
    float (*Ps)[65] = (float(*)[65])(smem + 3 * 64 * 65);

    int bh = blockIdx.y;
    int b = bh >> 4, h = bh & 15;
    int q0 = blockIdx.x * 64;
    int tid = threadIdx.x;
    int r  = tid >> 2;     // query row within tile
    int cg = tid & 3;      // 16-wide column group

    const float* qbase = qkv + (size_t)(b * SEQ + q0) * D3 + h * HS;
    #pragma unroll
    for (int t = 0; t < 4; t++) {
        int lid = tid + t * 256;
        int rr = lid >> 4, cc = (lid & 15) * 4;
        float4 qv = *(const float4*)(qbase + (size_t)rr * D3 + cc);
        Qs[rr][cc] = qv.x; Qs[rr][cc + 1] = qv.y; Qs[rr][cc + 2] = qv.z; Qs[rr][cc + 3] = qv.w;
    }
    float o[16];
    #pragma unroll
    for (int j = 0; j < 16; j++) o[j] = 0.f;
    float m = -1e30f, l = 0.f;

    const float* kbase = qkv + (size_t)(b * SEQ) * D3 + DIM + h * HS;
    const float* vbase = kbase + DIM;

    for (int kt = 0; kt < SEQ / 64; kt++) {
        __syncthreads();   // protect Ks/Vs from previous iteration readers
        #pragma unroll
        for (int t = 0; t < 4; t++) {
            int lid = tid + t * 256;
            int rr = lid >> 4, cc = (lid & 15) * 4;
            float4 kv = *(const float4*)(kbase + (size_t)(kt * 64 + rr) * D3 + cc);
            Ks[rr][cc] = kv.x; Ks[rr][cc + 1] = kv.y; Ks[rr][cc + 2] = kv.z; Ks[rr][cc + 3] = kv.w;
            float4 vv = *(const float4*)(vbase + (size_t)(kt * 64 + rr) * D3 + cc);
            Vs[rr][cc] = vv.x; Vs[rr][cc + 1] = vv.y; Vs[rr][cc + 2] = vv.z; Vs[rr][cc + 3] = vv.w;
        }
        __syncthreads();
        float s[16];
        #pragma unroll
        for (int c = 0; c < 16; c++) s[c] = 0.f;
        #pragma unroll
        for (int d = 0; d < 64; d++) {
            float qd = Qs[r][d];
            #pragma unroll
            for (int c = 0; c < 16; c++) s[c] += qd * Ks[cg * 16 + c][d];
        }
        float mt = -1e30f;
        #pragma unroll
        for (int c = 0; c < 16; c++) { s[c] *= 0.125f; mt = fmaxf(mt, s[c]); }
        mt = fmaxf(mt, __shfl_xor_sync(0xFFFFFFFFu, mt, 1));
        mt = fmaxf(mt, __shfl_xor_sync(0xFFFFFFFFu, mt, 2));
        float mnew = fmaxf(m, mt);
        float lt = 0.f;
        #pragma unroll
        for (int c = 0; c < 16; c++) { s[c] = __expf(s[c] - mnew); lt += s[c]; }
        lt += __shfl_xor_sync(0xFFFFFFFFu, lt, 1);
        lt += __shfl_xor_sync(0xFFFFFFFFu, lt, 2);
        float alpha = __expf(m - mnew);
        m = mnew;
        l = l * alpha + lt;
        #pragma unroll
        for (int j = 0; j < 16; j++) o[j] *= alpha;
        #pragma unroll
        for (int c = 0; c < 16; c++) Ps[r][cg * 16 + c] = s[c];
        __syncwarp();      // row's 4 producers are in the same warp
        #pragma unroll
        for (int kk = 0; kk < 64; kk++) {
            float p = Ps[r][kk];
            #pragma unroll
            for (int j = 0; j < 16; j++) o[j] += p * Vs[kk][cg * 16 + j];
        }
    }
    float inv = 1.0f / l;
    float* ob = attn_out + (size_t)(b * SEQ + q0 + r) * DIM + h * HS + cg * 16;
    #pragma unroll
    for (int t = 0; t < 4; t++) {
        float4 w4;
        w4.x = o[t*4+0] * inv; w4.y = o[t*4+1] * inv;
        w4.z = o[t*4+2] * inv; w4.w = o[t*4+3] * inv;
        *(float4*)(ob + t * 4) = w4;
    }
}

// ---------------- host orchestration ---------------------------------------
extern "C" void kernel_launch(void* const* d_in, const int* in_sizes, int n_in,
                              void* d_out, int out_size) {
    const float* x     = (const float*)d_in[0];
    const float* Wq    = (const float*)d_in[1];
    const float* bq    = (const float*)d_in[2];
    const float* Wk    = (const float*)d_in[3];
    const float* bk    = (const float*)d_in[4];
    const float* Wv    = (const float*)d_in[5];
    const float* bv    = (const float*)d_in[6];
    const float* Wproj = (const float*)d_in[7];
    const float* bproj = (const float*)d_in[8];
    const float* W1    = (const float*)d_in[9];
    const float* b1    = (const float*)d_in[10];
    const float* W2    = (const float*)d_in[11];
    const float* b2    = (const float*)d_in[12];
    const float* ln1_g = (const float*)d_in[13];
    const float* ln1_b = (const float*)d_in[14];
    const float* ln2_g = (const float*)d_in[15];
    const float* ln2_b = (const float*)d_in[16];
    float* out = (float*)d_out;

    float *h, *qkv, *attn, *x1, *ff, *wqkv, *bqkv;
    cudaGetSymbolAddress((void**)&h,    g_h);
    cudaGetSymbolAddress((void**)&qkv,  g_qkv);
    cudaGetSymbolAddress((void**)&attn, g_attn);
    cudaGetSymbolAddress((void**)&x1,   g_x1);
    cudaGetSymbolAddress((void**)&ff,   g_ff);
    cudaGetSymbolAddress((void**)&wqkv, g_wqkv);
    cudaGetSymbolAddress((void**)&bqkv, g_bqkv);

    const int FA_SMEM = 4 * 64 * 65 * (int)sizeof(float);  // 66560 B
    cudaFuncSetAttribute(flash_attn, cudaFuncAttributeMaxDynamicSharedMemorySize, FA_SMEM);

    // 1. pack per-head weights
    pack_qkv<<<(NH * DIM * HS + 255) / 256, 256>>>(Wq, Wk, Wv, bq, bk, bv);
    // 2. LN1
    ln_kernel<<<TOK, 256>>>(x, ln1_g, ln1_b, h);
    // 3. fused QKV gemm: [8192,1024] @ [1024,3072]
    {
        dim3 grid(D3 / 128, TOK / 128);
        sgemm<false, false><<<grid, 256>>>(h, wqkv, bqkv, nullptr, qkv, TOK, D3, DIM);
    }
    // 4. attention
    {
        dim3 grid(SEQ / 64, BATCH * NH);
        flash_attn<<<grid, 256, FA_SMEM>>>(qkv, attn);
    }
    // 5. proj + residual(x)
    {
        dim3 grid(DIM / 128, TOK / 128);
        sgemm<false, true><<<grid, 256>>>(attn, Wproj, bproj, x, x1, TOK, DIM, DIM);
    }
    // 6. LN2
    ln_kernel<<<TOK, 256>>>(x1, ln2_g, ln2_b, h);
    // 7. FF1 + LeakyReLU
    {
        dim3 grid(FFD / 128, TOK / 128);
        sgemm<true, false><<<grid, 256>>>(h, W1, b1, nullptr, ff, TOK, FFD, DIM);
    }
    // 8. FF2 + residual(x1) -> out
    {
        dim3 grid(DIM / 128, TOK / 128);
        sgemm<false, true><<<grid, 256>>>(ff, W2, b2, x1, out, TOK, DIM, FFD);
    }
}

// round 3
// speedup vs baseline: 1.6484x; 1.6484x over previous
#include <cuda_runtime.h>
#include <math.h>
#include <cstdint>

#define BATCH 8
#define SEQ 1024
#define DIM 1024
#define NH 16
#define HS 64
#define TOK (BATCH*SEQ)   // 8192
#define FFD (4*DIM)       // 4096
#define D3  (3*DIM)       // 3072

// ---------------- scratch (device globals; no allocation allowed) ----------
__device__ float g_h[TOK*DIM];           // LN output (reused)
__device__ float g_qkv[TOK*D3];          // fused q|k|v  [token][3072]
__device__ float g_attn[TOK*DIM];        // attention out, [B,N,H*HS]
__device__ float g_x1[TOK*DIM];          // x + attn@Wproj
__device__ float g_ff[(size_t)TOK*FFD];  // FF intermediate
__device__ float g_wqkvT[D3*DIM];        // [3072][1024]  row n = output col, K-major
__device__ float g_bqkv[D3];
__device__ float g_wprojT[DIM*DIM];      // [1024][1024]
__device__ float g_w1T[FFD*DIM];         // [4096][1024]
__device__ float g_w2T[DIM*FFD];         // [1024][4096]

// ======================= helpers ===========================================
__device__ __forceinline__ uint32_t smem_u32(const void* p) {
    uint32_t a;
    asm("{ .reg .u64 t; cvta.to.shared.u64 t, %1; cvt.u32.u64 %0, t; }" : "=r"(a) : "l"(p));
    return a;
}
__device__ __forceinline__ void cpa16(uint32_t dst, const void* src) {
    asm volatile("cp.async.cg.shared.global [%0], [%1], 16;\n" :: "r"(dst), "l"(src));
}
__device__ __forceinline__ void cp_commit() {
    asm volatile("cp.async.commit_group;" ::: "memory");
}
template<int N>
__device__ __forceinline__ void cp_wait() {
    asm volatile("cp.async.wait_group %0;" :: "n"(N) : "memory");
}
__device__ __forceinline__ void mma_tf32(float* c, const uint32_t* a, const uint32_t* b) {
    asm volatile(
        "mma.sync.aligned.m16n8k8.row.col.f32.tf32.tf32.f32 "
        "{%0,%1,%2,%3}, {%4,%5,%6,%7}, {%8,%9}, {%0,%1,%2,%3};"
        : "+f"(c[0]), "+f"(c[1]), "+f"(c[2]), "+f"(c[3])
        : "r"(a[0]), "r"(a[1]), "r"(a[2]), "r"(a[3]), "r"(b[0]), "r"(b[1]));
}

// ======================= weight transpose ==================================
// in: [Z][R][C] -> out: [Z][C][R]
__global__ void batched_transpose(const float* __restrict__ in, float* __restrict__ out,
                                  int R, int C) {
    __shared__ float t[32][33];
    int z = blockIdx.z;
    const float* iz = in + (size_t)z * R * C;
    float* oz = out + (size_t)z * R * C;
    int bx = blockIdx.x * 32;  // col tile
    int by = blockIdx.y * 32;  // row tile
    int x = bx + threadIdx.x;
    #pragma unroll
    for (int i = threadIdx.y; i < 32; i += 8)
        t[i][threadIdx.x] = iz[(size_t)(by + i) * C + x];
    __syncthreads();
    int ox = by + threadIdx.x;
    #pragma unroll
    for (int i = threadIdx.y; i < 32; i += 8)
        oz[(size_t)(bx + i) * R + ox] = t[threadIdx.x][i];
}

__global__ void pack_bias(const float* __restrict__ bq, const float* __restrict__ bk,
                          const float* __restrict__ bv) {
    int i = blockIdx.x * blockDim.x + threadIdx.x;
    if (i < DIM) {
        g_bqkv[i]         = bq[i];
        g_bqkv[i + DIM]   = bk[i];
        g_bqkv[i + 2*DIM] = bv[i];
    }
}

// ---------------- layernorm: one block (256 thr) per row of 1024 -----------
__global__ void ln_kernel(const float* __restrict__ x, const float* __restrict__ g,
                          const float* __restrict__ b, float* __restrict__ out) {
    int row = blockIdx.x;
    const float4* xr = (const float4*)(x + (size_t)row * DIM);
    float4 v = xr[threadIdx.x];
    float s  = v.x + v.y + v.z + v.w;
    float ss = v.x*v.x + v.y*v.y + v.z*v.z + v.w*v.w;
    #pragma unroll
    for (int o = 16; o; o >>= 1) {
        s  += __shfl_xor_sync(0xFFFFFFFFu, s, o);
        ss += __shfl_xor_sync(0xFFFFFFFFu, ss, o);
    }
    __shared__ float sm[8], sm2[8];
    int w = threadIdx.x >> 5, l = threadIdx.x & 31;
    if (l == 0) { sm[w] = s; sm2[w] = ss; }
    __syncthreads();
    if (w == 0) {
        s  = (l < 8) ? sm[l]  : 0.f;
        ss = (l < 8) ? sm2[l] : 0.f;
        #pragma unroll
        for (int o = 4; o; o >>= 1) {
            s  += __shfl_xor_sync(0xFFFFFFFFu, s, o);
            ss += __shfl_xor_sync(0xFFFFFFFFu, ss, o);
        }
        if (l == 0) { sm[0] = s; sm2[0] = ss; }
    }
    __syncthreads();
    float mu   = sm[0] * (1.0f / DIM);
    float var  = sm2[0] * (1.0f / DIM) - mu * mu;
    float rstd = rsqrtf(var + 1e-5f);
    float4 gg = ((const float4*)g)[threadIdx.x];
    float4 bb = ((const float4*)b)[threadIdx.x];
    float4 o4;
    o4.x = (v.x - mu) * rstd * gg.x + bb.x;
    o4.y = (v.y - mu) * rstd * gg.y + bb.y;
    o4.z = (v.z - mu) * rstd * gg.z + bb.z;
    o4.w = (v.w - mu) * rstd * gg.w + bb.w;
    ((float4*)(out + (size_t)row * DIM))[threadIdx.x] = o4;
}

// ======================= tf32 mma.sync GEMM ================================
// C[M,N] = epi(A[M,K] @ Bt[N,K]^T + bias[N]) (+res)
// CTA tile 128x128, warp tile 32x64 (4x2 warps), K-chunk 32, 3-stage cp.async
#define KC 32
#define ASTRIDE 36                       // floats per smem row (pad 32->36)
#define TILE_F (128 * ASTRIDE)           // floats per A (or B) stage
#define GSTAGES 3
#define GEMM_SMEM (GSTAGES * 2 * TILE_F * 4)  // 110592 bytes

__device__ __forceinline__ void load_chunk(int tid, uint32_t as, uint32_t bs,
                                           const float* Aj, const float* Bj, int K) {
    #pragma unroll
    for (int t = 0; t < 4; t++) {
        int v = tid + t * 256;
        int row = v >> 3, seg = v & 7;
        cpa16(as + (row * ASTRIDE + seg * 4) * 4, Aj + (size_t)row * K + seg * 4);
    }
    #pragma unroll
    for (int t = 0; t < 4; t++) {
        int v = tid + t * 256;
        int row = v >> 3, seg = v & 7;
        cpa16(bs + (row * ASTRIDE + seg * 4) * 4, Bj + (size_t)row * K + seg * 4);
    }
}

template<int EPI>   // 0 = bias, 1 = bias+res, 2 = bias+leaky
__global__ __launch_bounds__(256)
void gemm_mma(const float* __restrict__ A, const float* __restrict__ Bt,
              const float* __restrict__ bias, const float* __restrict__ res,
              float* __restrict__ C, int M, int N, int K) {
    extern __shared__ float smem[];
    uint32_t sb = smem_u32(smem);
    int tid = threadIdx.x;
    int wid = tid >> 5, lane = tid & 31;
    int grp = lane >> 2, tig = lane & 3;
    int wm = wid & 3, wn = wid >> 2;     // warp tile: rows 32*wm, cols 64*wn
    int bn = blockIdx.x, bm = blockIdx.y;
    int nch = K >> 5;

    const float* Ag = A + (size_t)bm * 128 * K;
    const float* Bg = Bt + (size_t)bn * 128 * K;

    // prologue
    #pragma unroll
    for (int j = 0; j < GSTAGES; j++) {
        uint32_t st = sb + j * (2 * TILE_F * 4);
        load_chunk(tid, st, st + TILE_F * 4, Ag + j * KC, Bg + j * KC, K);
        cp_commit();
    }

    float acc[2][8][4];
    #pragma unroll
    for (int i = 0; i < 2; i++)
        #pragma unroll
        for (int j = 0; j < 8; j++)
            #pragma unroll
            for (int q = 0; q < 4; q++) acc[i][j][q] = 0.f;

    for (int ch = 0; ch < nch; ch++) {
        int s = ch % GSTAGES;
        const float* As = smem + s * 2 * TILE_F;
        const float* Bs = As + TILE_F;
        cp_wait<GSTAGES - 1>();
        __syncthreads();
        #pragma unroll
        for (int kk = 0; kk < 4; kk++) {
            int k = kk * 8;
            uint32_t a[2][4], b[8][2];
            #pragma unroll
            for (int i = 0; i < 2; i++) {
                const float* ar = As + (wm * 32 + i * 16 + grp) * ASTRIDE + k + tig;
                a[i][0] = __float_as_uint(ar[0]);
                a[i][2] = __float_as_uint(ar[4]);
                a[i][1] = __float_as_uint(ar[8 * ASTRIDE]);
                a[i][3] = __float_as_uint(ar[8 * ASTRIDE + 4]);
            }
            #pragma unroll
            for (int j = 0; j < 8; j++) {
                const float* br = Bs + (wn * 64 + j * 8 + grp) * ASTRIDE + k + tig;
                b[j][0] = __float_as_uint(br[0]);
                b[j][1] = __float_as_uint(br[4]);
            }
            #pragma unroll
            for (int i = 0; i < 2; i++)
                #pragma unroll
                for (int j = 0; j < 8; j++)
                    mma_tf32(acc[i][j], a[i], b[j]);
        }
        __syncthreads();
        if (ch + GSTAGES < nch) {
            uint32_t st = sb + s * (2 * TILE_F * 4);
            load_chunk(tid, st, st + TILE_F * 4,
                       Ag + (ch + GSTAGES) * KC, Bg + (ch + GSTAGES) * KC, K);
        }
        cp_commit();
    }

    // epilogue: direct register -> gmem
    #pragma unroll
    for (int i = 0; i < 2; i++) {
        int row0 = bm * 128 + wm * 32 + i * 16 + grp;
        #pragma unroll
        for (int j = 0; j < 8; j++) {
            int col = bn * 128 + wn * 64 + j * 8 + tig * 2;
            float b0 = bias[col], b1 = bias[col + 1];
            #pragma unroll
            for (int half = 0; half < 2; half++) {
                int row = row0 + half * 8;
                float v0 = acc[i][j][2 * half]     + b0;
                float v1 = acc[i][j][2 * half + 1] + b1;
                if (EPI == 2) {
                    v0 = v0 > 0.f ? v0 : 0.01f * v0;
                    v1 = v1 > 0.f ? v1 : 0.01f * v1;
                }
                if (EPI == 1) {
                    float2 rv = *(const float2*)(res + (size_t)row * N + col);
                    v0 += rv.x; v1 += rv.y;
                }
                float2 w2; w2.x = v0; w2.y = v1;
                *(float2*)(C + (size_t)row * N + col) = w2;
            }
        }
    }
}

// ---------------- flash attention (unchanged) ------------------------------
__global__ __launch_bounds__(256)
void flash_attn(const float* __restrict__ qkv, float* __restrict__ attn_out) {
    extern __shared__ float fsmem[];
    float (*Qs)[65] = (float(*)[65])fsmem;
    float (*Ks)[65] = (float(*)[65])(fsmem + 64 * 65);
    float (*Vs)[65] = (float(*)[65])(fsmem + 2 * 64 * 65);
    float (*Ps)[65] = (float(*)[65])(fsmem + 3 * 64 * 65);

    int bh = blockIdx.y;
    int b = bh >> 4, h = bh & 15;
    int q0 = blockIdx.x * 64;
    int tid = threadIdx.x;
    int r  = tid >> 2;
    int cg = tid & 3;

    const float* qbase = qkv + (size_t)(b * SEQ + q0) * D3 + h * HS;
    #pragma unroll
    for (int t = 0; t < 4; t++) {
        int lid = tid + t * 256;
        int rr = lid >> 4, cc = (lid & 15) * 4;
        float4 qv = *(const float4*)(qbase + (size_t)rr * D3 + cc);
        Qs[rr][cc] = qv.x; Qs[rr][cc + 1] = qv.y; Qs[rr][cc + 2] = qv.z; Qs[rr][cc + 3] = qv.w;
    }
    float o[16];
    #pragma unroll
    for (int j = 0; j < 16; j++) o[j] = 0.f;
    float m = -1e30f, l = 0.f;

    const float* kbase = qkv + (size_t)(b * SEQ) * D3 + DIM + h * HS;
    const float* vbase = kbase + DIM;

    for (int kt = 0; kt < SEQ / 64; kt++) {
        __syncthreads();
        #pragma unroll
        for (int t = 0; t < 4; t++) {
            int lid = tid + t * 256;
            int rr = lid >> 4, cc = (lid & 15) * 4;
            float4 kv = *(const float4*)(kbase + (size_t)(kt * 64 + rr) * D3 + cc);
            Ks[rr][cc] = kv.x; Ks[rr][cc + 1] = kv.y; Ks[rr][cc + 2] = kv.z; Ks[rr][cc + 3] = kv.w;
            float4 vv = *(const float4*)(vbase + (size_t)(kt * 64 + rr) * D3 + cc);
            Vs[rr][cc] = vv.x; Vs[rr][cc + 1] = vv.y; Vs[rr][cc + 2] = vv.z; Vs[rr][cc + 3] = vv.w;
        }
        __syncthreads();
        float s[16];
        #pragma unroll
        for (int c = 0; c < 16; c++) s[c] = 0.f;
        #pragma unroll
        for (int d = 0; d < 64; d++) {
            float qd = Qs[r][d];
            #pragma unroll
            for (int c = 0; c < 16; c++) s[c] += qd * Ks[cg * 16 + c][d];
        }
        float mt = -1e30f;
        #pragma unroll
        for (int c = 0; c < 16; c++) { s[c] *= 0.125f; mt = fmaxf(mt, s[c]); }
        mt = fmaxf(mt, __shfl_xor_sync(0xFFFFFFFFu, mt, 1));
        mt = fmaxf(mt, __shfl_xor_sync(0xFFFFFFFFu, mt, 2));
        float mnew = fmaxf(m, mt);
        float lt = 0.f;
        #pragma unroll
        for (int c = 0; c < 16; c++) { s[c] = __expf(s[c] - mnew); lt += s[c]; }
        lt += __shfl_xor_sync(0xFFFFFFFFu, lt, 1);
        lt += __shfl_xor_sync(0xFFFFFFFFu, lt, 2);
        float alpha = __expf(m - mnew);
        m = mnew;
        l = l * alpha + lt;
        #pragma unroll
        for (int j = 0; j < 16; j++) o[j] *= alpha;
        #pragma unroll
        for (int c = 0; c < 16; c++) Ps[r][cg * 16 + c] = s[c];
        __syncwarp();
        #pragma unroll
        for (int kk = 0; kk < 64; kk++) {
            float p = Ps[r][kk];
            #pragma unroll
            for (int j = 0; j < 16; j++) o[j] += p * Vs[kk][cg * 16 + j];
        }
    }
    float inv = 1.0f / l;
    float* ob = attn_out + (size_t)(b * SEQ + q0 + r) * DIM + h * HS + cg * 16;
    #pragma unroll
    for (int t = 0; t < 4; t++) {
        float4 w4;
        w4.x = o[t*4+0] * inv; w4.y = o[t*4+1] * inv;
        w4.z = o[t*4+2] * inv; w4.w = o[t*4+3] * inv;
        *(float4*)(ob + t * 4) = w4;
    }
}

// ---------------- host orchestration ---------------------------------------
extern "C" void kernel_launch(void* const* d_in, const int* in_sizes, int n_in,
                              void* d_out, int out_size) {
    const float* x     = (const float*)d_in[0];
    const float* Wq    = (const float*)d_in[1];
    const float* bq    = (const float*)d_in[2];
    const float* Wk    = (const float*)d_in[3];
    const float* bk    = (const float*)d_in[4];
    const float* Wv    = (const float*)d_in[5];
    const float* bv    = (const float*)d_in[6];
    const float* Wproj = (const float*)d_in[7];
    const float* bproj = (const float*)d_in[8];
    const float* W1    = (const float*)d_in[9];
    const float* b1    = (const float*)d_in[10];
    const float* W2    = (const float*)d_in[11];
    const float* b2    = (const float*)d_in[12];
    const float* ln1_g = (const float*)d_in[13];
    const float* ln1_b = (const float*)d_in[14];
    const float* ln2_g = (const float*)d_in[15];
    const float* ln2_b = (const float*)d_in[16];
    float* out = (float*)d_out;

    float *h, *qkv, *attn, *x1, *ff, *wqkvT, *wprojT, *w1T, *w2T, *bqkv;
    cudaGetSymbolAddress((void**)&h,      g_h);
    cudaGetSymbolAddress((void**)&qkv,    g_qkv);
    cudaGetSymbolAddress((void**)&attn,   g_attn);
    cudaGetSymbolAddress((void**)&x1,     g_x1);
    cudaGetSymbolAddress((void**)&ff,     g_ff);
    cudaGetSymbolAddress((void**)&wqkvT,  g_wqkvT);
    cudaGetSymbolAddress((void**)&wprojT, g_wprojT);
    cudaGetSymbolAddress((void**)&w1T,    g_w1T);
    cudaGetSymbolAddress((void**)&w2T,    g_w2T);
    cudaGetSymbolAddress((void**)&bqkv,   g_bqkv);

    const int FA_SMEM = 4 * 64 * 65 * (int)sizeof(float);
    cudaFuncSetAttribute(flash_attn, cudaFuncAttributeMaxDynamicSharedMemorySize, FA_SMEM);
    cudaFuncSetAttribute(gemm_mma<0>, cudaFuncAttributeMaxDynamicSharedMemorySize, GEMM_SMEM);
    cudaFuncSetAttribute(gemm_mma<1>, cudaFuncAttributeMaxDynamicSharedMemorySize, GEMM_SMEM);
    cudaFuncSetAttribute(gemm_mma<2>, cudaFuncAttributeMaxDynamicSharedMemorySize, GEMM_SMEM);

    dim3 tb(32, 8);
    // per-head qkv transposes: in [H][D][HS] -> out [H][HS][D] stacked as [3072][1024]
    batched_transpose<<<dim3(HS/32, DIM/32, NH), tb>>>(Wq, wqkvT,              DIM, HS);
    batched_transpose<<<dim3(HS/32, DIM/32, NH), tb>>>(Wk, wqkvT + DIM*DIM,    DIM, HS);
    batched_transpose<<<dim3(HS/32, DIM/32, NH), tb>>>(Wv, wqkvT + 2*DIM*DIM,  DIM, HS);
    batched_transpose<<<dim3(DIM/32, DIM/32, 1), tb>>>(Wproj, wprojT, DIM, DIM);
    batched_transpose<<<dim3(FFD/32, DIM/32, 1), tb>>>(W1, w1T, DIM, FFD);
    batched_transpose<<<dim3(DIM/32, FFD/32, 1), tb>>>(W2, w2T, FFD, DIM);
    pack_bias<<<(DIM + 255) / 256, 256>>>(bq, bk, bv);

    // 1. LN1
    ln_kernel<<<TOK, 256>>>(x, ln1_g, ln1_b, h);
    // 2. QKV: [8192,1024] @ [1024,3072]
    gemm_mma<0><<<dim3(D3/128, TOK/128), 256, GEMM_SMEM>>>(h, wqkvT, bqkv, nullptr, qkv, TOK, D3, DIM);
    // 3. attention
    flash_attn<<<dim3(SEQ/64, BATCH*NH), 256, FA_SMEM>>>(qkv, attn);
    // 4. proj + residual(x)
    gemm_mma<1><<<dim3(DIM/128, TOK/128), 256, GEMM_SMEM>>>(attn, wprojT, bproj, x, x1, TOK, DIM, DIM);
    // 5. LN2
    ln_kernel<<<TOK, 256>>>(x1, ln2_g, ln2_b, h);
    // 6. FF1 + LeakyReLU
    gemm_mma<2><<<dim3(FFD/128, TOK/128), 256, GEMM_SMEM>>>(h, w1T, b1, nullptr, ff, TOK, FFD, DIM);
    // 7. FF2 + residual(x1) -> out
    gemm_mma<1><<<dim3(DIM/128, TOK/128), 256, GEMM_SMEM>>>(ff, w2T, b2, x1, out, TOK, DIM, FFD);
}

// round 4
// speedup vs baseline: 2.4719x; 1.4996x over previous
#include <cuda_runtime.h>
#include <math.h>
#include <cstdint>

#define BATCH 8
#define SEQ 1024
#define DIM 1024
#define NH 16
#define HS 64
#define TOK (BATCH*SEQ)   // 8192
#define FFD (4*DIM)       // 4096
#define D3  (3*DIM)       // 3072

// ---------------- scratch (device globals; no allocation allowed) ----------
__device__ float g_h[TOK*DIM];           // LN output (reused)
__device__ float g_qkv[TOK*D3];          // fused q|k|v  [token][3072]
__device__ float g_attn[TOK*DIM];        // attention out, [B,N,H*HS]
__device__ float g_x1[TOK*DIM];          // x + attn@Wproj
__device__ float g_ff[(size_t)TOK*FFD];  // FF intermediate
__device__ float g_wqkvT[D3*DIM];        // [3072][1024]
__device__ float g_bqkv[D3];
__device__ float g_wprojT[DIM*DIM];
__device__ float g_w1T[FFD*DIM];
__device__ float g_w2T[DIM*FFD];

// ======================= helpers ===========================================
__device__ __forceinline__ uint32_t smem_u32(const void* p) {
    uint32_t a;
    asm("{ .reg .u64 t; cvta.to.shared.u64 t, %1; cvt.u32.u64 %0, t; }" : "=r"(a) : "l"(p));
    return a;
}
__device__ __forceinline__ void cpa16(uint32_t dst, const void* src) {
    asm volatile("cp.async.cg.shared.global [%0], [%1], 16;\n" :: "r"(dst), "l"(src));
}
__device__ __forceinline__ void cp_commit() {
    asm volatile("cp.async.commit_group;" ::: "memory");
}
template<int N>
__device__ __forceinline__ void cp_wait() {
    asm volatile("cp.async.wait_group %0;" :: "n"(N) : "memory");
}
__device__ __forceinline__ void mma_tf32(float* c, const uint32_t* a, const uint32_t* b) {
    asm volatile(
        "mma.sync.aligned.m16n8k8.row.col.f32.tf32.tf32.f32 "
        "{%0,%1,%2,%3}, {%4,%5,%6,%7}, {%8,%9}, {%0,%1,%2,%3};"
        : "+f"(c[0]), "+f"(c[1]), "+f"(c[2]), "+f"(c[3])
        : "r"(a[0]), "r"(a[1]), "r"(a[2]), "r"(a[3]), "r"(b[0]), "r"(b[1]));
}

// ======================= weight transpose ==================================
__global__ void batched_transpose(const float* __restrict__ in, float* __restrict__ out,
                                  int R, int C) {
    __shared__ float t[32][33];
    int z = blockIdx.z;
    const float* iz = in + (size_t)z * R * C;
    float* oz = out + (size_t)z * R * C;
    int bx = blockIdx.x * 32;
    int by = blockIdx.y * 32;
    int x = bx + threadIdx.x;
    #pragma unroll
    for (int i = threadIdx.y; i < 32; i += 8)
        t[i][threadIdx.x] = iz[(size_t)(by + i) * C + x];
    __syncthreads();
    int ox = by + threadIdx.x;
    #pragma unroll
    for (int i = threadIdx.y; i < 32; i += 8)
        oz[(size_t)(bx + i) * R + ox] = t[threadIdx.x][i];
}

__global__ void pack_bias(const float* __restrict__ bq, const float* __restrict__ bk,
                          const float* __restrict__ bv) {
    int i = blockIdx.x * blockDim.x + threadIdx.x;
    if (i < DIM) {
        g_bqkv[i]         = bq[i];
        g_bqkv[i + DIM]   = bk[i];
        g_bqkv[i + 2*DIM] = bv[i];
    }
}

// ---------------- layernorm ------------------------------------------------
__global__ void ln_kernel(const float* __restrict__ x, const float* __restrict__ g,
                          const float* __restrict__ b, float* __restrict__ out) {
    int row = blockIdx.x;
    const float4* xr = (const float4*)(x + (size_t)row * DIM);
    float4 v = xr[threadIdx.x];
    float s  = v.x + v.y + v.z + v.w;
    float ss = v.x*v.x + v.y*v.y + v.z*v.z + v.w*v.w;
    #pragma unroll
    for (int o = 16; o; o >>= 1) {
        s  += __shfl_xor_sync(0xFFFFFFFFu, s, o);
        ss += __shfl_xor_sync(0xFFFFFFFFu, ss, o);
    }
    __shared__ float sm[8], sm2[8];
    int w = threadIdx.x >> 5, l = threadIdx.x & 31;
    if (l == 0) { sm[w] = s; sm2[w] = ss; }
    __syncthreads();
    if (w == 0) {
        s  = (l < 8) ? sm[l]  : 0.f;
        ss = (l < 8) ? sm2[l] : 0.f;
        #pragma unroll
        for (int o = 4; o; o >>= 1) {
            s  += __shfl_xor_sync(0xFFFFFFFFu, s, o);
            ss += __shfl_xor_sync(0xFFFFFFFFu, ss, o);
        }
        if (l == 0) { sm[0] = s; sm2[0] = ss; }
    }
    __syncthreads();
    float mu   = sm[0] * (1.0f / DIM);
    float var  = sm2[0] * (1.0f / DIM) - mu * mu;
    float rstd = rsqrtf(var + 1e-5f);
    float4 gg = ((const float4*)g)[threadIdx.x];
    float4 bb = ((const float4*)b)[threadIdx.x];
    float4 o4;
    o4.x = (v.x - mu) * rstd * gg.x + bb.x;
    o4.y = (v.y - mu) * rstd * gg.y + bb.y;
    o4.z = (v.z - mu) * rstd * gg.z + bb.z;
    o4.w = (v.w - mu) * rstd * gg.w + bb.w;
    ((float4*)(out + (size_t)row * DIM))[threadIdx.x] = o4;
}

// ======================= tf32 mma.sync GEMM ================================
// CTA tile 128x256, 8 warps (2m x 4n), warp tile 64x64, K-chunk 32, 3 stages
#define KC 32
#define ASTRIDE 36
#define A_ST_F (128 * ASTRIDE)               // 4608 floats
#define B_ST_F (256 * ASTRIDE)               // 9216 floats
#define STG_F (A_ST_F + B_ST_F)              // 13824 floats
#define GSTAGES 3
#define GEMM_SMEM (GSTAGES * STG_F * 4)      // 165888 bytes

__device__ __forceinline__ void load_chunk(int tid, uint32_t as, uint32_t bs,
                                           const float* Aj, const float* Bj, int K) {
    #pragma unroll
    for (int t = 0; t < 4; t++) {
        int v = tid + t * 256;
        int row = v >> 3, seg = v & 7;
        cpa16(as + (row * ASTRIDE + seg * 4) * 4, Aj + (size_t)row * K + seg * 4);
    }
    #pragma unroll
    for (int t = 0; t < 8; t++) {
        int v = tid + t * 256;
        int row = v >> 3, seg = v & 7;
        cpa16(bs + (row * ASTRIDE + seg * 4) * 4, Bj + (size_t)row * K + seg * 4);
    }
}

template<int EPI>   // 0 = bias, 1 = bias+res, 2 = bias+leaky
__global__ __launch_bounds__(256, 1)
void gemm_mma(const float* __restrict__ A, const float* __restrict__ Bt,
              const float* __restrict__ bias, const float* __restrict__ res,
              float* __restrict__ C, int M, int N, int K) {
    extern __shared__ float smem[];
    uint32_t sb = smem_u32(smem);
    int tid = threadIdx.x;
    int wid = tid >> 5, lane = tid & 31;
    int grp = lane >> 2, tig = lane & 3;
    int wm = wid & 1, wn = wid >> 1;     // warp tile: rows 64*wm, cols 64*wn
    int bn = blockIdx.x, bm = blockIdx.y;
    int nch = K >> 5;

    const float* Ag = A + (size_t)bm * 128 * K;
    const float* Bg = Bt + (size_t)bn * 256 * K;

    #pragma unroll
    for (int j = 0; j < GSTAGES; j++) {
        uint32_t st = sb + j * (STG_F * 4);
        load_chunk(tid, st, st + A_ST_F * 4, Ag + j * KC, Bg + j * KC, K);
        cp_commit();
    }

    float acc[4][8][4];
    #pragma unroll
    for (int i = 0; i < 4; i++)
        #pragma unroll
        for (int j = 0; j < 8; j++)
            #pragma unroll
            for (int q = 0; q < 4; q++) acc[i][j][q] = 0.f;

    for (int ch = 0; ch < nch; ch++) {
        int s = ch % GSTAGES;
        const float* As = smem + s * STG_F;
        const float* Bs = As + A_ST_F;
        cp_wait<GSTAGES - 1>();
        __syncthreads();
        #pragma unroll
        for (int kk = 0; kk < 4; kk++) {
            int k = kk * 8;
            uint32_t a[4][4], b[8][2];
            #pragma unroll
            for (int i = 0; i < 4; i++) {
                const float* ar = As + (wm * 64 + i * 16 + grp) * ASTRIDE + k + tig;
                a[i][0] = __float_as_uint(ar[0]);
                a[i][2] = __float_as_uint(ar[4]);
                a[i][1] = __float_as_uint(ar[8 * ASTRIDE]);
                a[i][3] = __float_as_uint(ar[8 * ASTRIDE + 4]);
            }
            #pragma unroll
            for (int j = 0; j < 8; j++) {
                const float* br = Bs + (wn * 64 + j * 8 + grp) * ASTRIDE + k + tig;
                b[j][0] = __float_as_uint(br[0]);
                b[j][1] = __float_as_uint(br[4]);
            }
            #pragma unroll
            for (int i = 0; i < 4; i++)
                #pragma unroll
                for (int j = 0; j < 8; j++)
                    mma_tf32(acc[i][j], a[i], b[j]);
        }
        __syncthreads();
        if (ch + GSTAGES < nch) {
            uint32_t st = sb + s * (STG_F * 4);
            load_chunk(tid, st, st + A_ST_F * 4,
                       Ag + (ch + GSTAGES) * KC, Bg + (ch + GSTAGES) * KC, K);
        }
        cp_commit();
    }

    // epilogue
    #pragma unroll
    for (int i = 0; i < 4; i++) {
        int row0 = bm * 128 + wm * 64 + i * 16 + grp;
        #pragma unroll
        for (int j = 0; j < 8; j++) {
            int col = bn * 256 + wn * 64 + j * 8 + tig * 2;
            float b0 = bias[col], b1 = bias[col + 1];
            #pragma unroll
            for (int half = 0; half < 2; half++) {
                int row = row0 + half * 8;
                float v0 = acc[i][j][2 * half]     + b0;
                float v1 = acc[i][j][2 * half + 1] + b1;
                if (EPI == 2) {
                    v0 = v0 > 0.f ? v0 : 0.01f * v0;
                    v1 = v1 > 0.f ? v1 : 0.01f * v1;
                }
                if (EPI == 1) {
                    float2 rv = *(const float2*)(res + (size_t)row * N + col);
                    v0 += rv.x; v1 += rv.y;
                }
                float2 w2; w2.x = v0; w2.y = v1;
                *(float2*)(C + (size_t)row * N + col) = w2;
            }
        }
    }
}

// ======================= flash attention (register tiled) ==================
// q-tile 128, key-tile 64. 256 threads: thread = (rgrp 0..63, cgrp 0..3),
// owns q-rows {2*rgrp, 2*rgrp+1} x k-cols [cgrp*16, cgrp*16+16)
#define FA_SMEM_F (128*65 + 64*65 + 64*65 + 128*65)   // Qs, Ks, Vs, Ps
#define FA_SMEM_B (FA_SMEM_F * 4)                      // 100,480 bytes

__global__ __launch_bounds__(256)
void flash_attn(const float* __restrict__ qkv, float* __restrict__ attn_out) {
    extern __shared__ float fsmem[];
    float (*Qs)[65] = (float(*)[65])fsmem;
    float (*Ks)[65] = (float(*)[65])(fsmem + 128 * 65);
    float (*Vs)[65] = (float(*)[65])(fsmem + 128 * 65 + 64 * 65);
    float (*Ps)[65] = (float(*)[65])(fsmem + 128 * 65 + 2 * 64 * 65);

    int bh = blockIdx.y;
    int b = bh >> 4, h = bh & 15;
    int q0 = blockIdx.x * 128;
    int tid = threadIdx.x;
    int rgrp = tid >> 2, cgrp = tid & 3;
    int r0 = rgrp * 2;

    const float* qbase = qkv + (size_t)(b * SEQ + q0) * D3 + h * HS;
    #pragma unroll
    for (int t = 0; t < 8; t++) {
        int lid = tid + t * 256;
        int rr = lid >> 4, cc = (lid & 15) * 4;
        float4 qv = *(const float4*)(qbase + (size_t)rr * D3 + cc);
        Qs[rr][cc] = qv.x; Qs[rr][cc+1] = qv.y; Qs[rr][cc+2] = qv.z; Qs[rr][cc+3] = qv.w;
    }

    float o[2][16];
    #pragma unroll
    for (int rr = 0; rr < 2; rr++)
        #pragma unroll
        for (int j = 0; j < 16; j++) o[rr][j] = 0.f;
    float m[2] = {-1e30f, -1e30f}, l[2] = {0.f, 0.f};

    const float* kbase = qkv + (size_t)(b * SEQ) * D3 + DIM + h * HS;
    const float* vbase = kbase + DIM;

    for (int kt = 0; kt < SEQ / 64; kt++) {
        __syncthreads();
        #pragma unroll
        for (int t = 0; t < 4; t++) {
            int lid = tid + t * 256;
            int rr = lid >> 4, cc = (lid & 15) * 4;
            float4 kv = *(const float4*)(kbase + (size_t)(kt * 64 + rr) * D3 + cc);
            Ks[rr][cc] = kv.x; Ks[rr][cc+1] = kv.y; Ks[rr][cc+2] = kv.z; Ks[rr][cc+3] = kv.w;
            float4 vv = *(const float4*)(vbase + (size_t)(kt * 64 + rr) * D3 + cc);
            Vs[rr][cc] = vv.x; Vs[rr][cc+1] = vv.y; Vs[rr][cc+2] = vv.z; Vs[rr][cc+3] = vv.w;
        }
        __syncthreads();

        float s[2][16];
        #pragma unroll
        for (int rr = 0; rr < 2; rr++)
            #pragma unroll
            for (int c = 0; c < 16; c++) s[rr][c] = 0.f;
        #pragma unroll 4
        for (int d = 0; d < 64; d++) {
            float q0v = Qs[r0][d];
            float q1v = Qs[r0 + 1][d];
            #pragma unroll
            for (int c = 0; c < 16; c++) {
                float kv = Ks[cgrp * 16 + c][d];
                s[0][c] += q0v * kv;
                s[1][c] += q1v * kv;
            }
        }

        #pragma unroll
        for (int rr = 0; rr < 2; rr++) {
            float mt = -1e30f;
            #pragma unroll
            for (int c = 0; c < 16; c++) { s[rr][c] *= 0.125f; mt = fmaxf(mt, s[rr][c]); }
            mt = fmaxf(mt, __shfl_xor_sync(0xFFFFFFFFu, mt, 1));
            mt = fmaxf(mt, __shfl_xor_sync(0xFFFFFFFFu, mt, 2));
            float mnew = fmaxf(m[rr], mt);
            float lt = 0.f;
            #pragma unroll
            for (int c = 0; c < 16; c++) { s[rr][c] = __expf(s[rr][c] - mnew); lt += s[rr][c]; }
            lt += __shfl_xor_sync(0xFFFFFFFFu, lt, 1);
            lt += __shfl_xor_sync(0xFFFFFFFFu, lt, 2);
            float alpha = __expf(m[rr] - mnew);
            m[rr] = mnew;
            l[rr] = l[rr] * alpha + lt;
            #pragma unroll
            for (int j = 0; j < 16; j++) o[rr][j] *= alpha;
            #pragma unroll
            for (int c = 0; c < 16; c++) Ps[r0 + rr][cgrp * 16 + c] = s[rr][c];
        }
        __syncwarp();
        #pragma unroll 4
        for (int kk = 0; kk < 64; kk++) {
            float p0 = Ps[r0][kk];
            float p1 = Ps[r0 + 1][kk];
            #pragma unroll
            for (int j = 0; j < 16; j++) {
                float vv = Vs[kk][cgrp * 16 + j];
                o[0][j] += p0 * vv;
                o[1][j] += p1 * vv;
            }
        }
    }

    #pragma unroll
    for (int rr = 0; rr < 2; rr++) {
        float inv = 1.0f / l[rr];
        float* ob = attn_out + (size_t)(b * SEQ + q0 + r0 + rr) * DIM + h * HS + cgrp * 16;
        #pragma unroll
        for (int t = 0; t < 4; t++) {
            float4 w4;
            w4.x = o[rr][t*4+0] * inv; w4.y = o[rr][t*4+1] * inv;
            w4.z = o[rr][t*4+2] * inv; w4.w = o[rr][t*4+3] * inv;
            *(float4*)(ob + t * 4) = w4;
        }
    }
}

// ---------------- host orchestration ---------------------------------------
extern "C" void kernel_launch(void* const* d_in, const int* in_sizes, int n_in,
                              void* d_out, int out_size) {
    const float* x     = (const float*)d_in[0];
    const float* Wq    = (const float*)d_in[1];
    const float* bq    = (const float*)d_in[2];
    const float* Wk    = (const float*)d_in[3];
    const float* bk    = (const float*)d_in[4];
    const float* Wv    = (const float*)d_in[5];
    const float* bv    = (const float*)d_in[6];
    const float* Wproj = (const float*)d_in[7];
    const float* bproj = (const float*)d_in[8];
    const float* W1    = (const float*)d_in[9];
    const float* b1    = (const float*)d_in[10];
    const float* W2    = (const float*)d_in[11];
    const float* b2    = (const float*)d_in[12];
    const float* ln1_g = (const float*)d_in[13];
    const float* ln1_b = (const float*)d_in[14];
    const float* ln2_g = (const float*)d_in[15];
    const float* ln2_b = (const float*)d_in[16];
    float* out = (float*)d_out;

    float *h, *qkv, *attn, *x1, *ff, *wqkvT, *wprojT, *w1T, *w2T, *bqkv;
    cudaGetSymbolAddress((void**)&h,      g_h);
    cudaGetSymbolAddress((void**)&qkv,    g_qkv);
    cudaGetSymbolAddress((void**)&attn,   g_attn);
    cudaGetSymbolAddress((void**)&x1,     g_x1);
    cudaGetSymbolAddress((void**)&ff,     g_ff);
    cudaGetSymbolAddress((void**)&wqkvT,  g_wqkvT);
    cudaGetSymbolAddress((void**)&wprojT, g_wprojT);
    cudaGetSymbolAddress((void**)&w1T,    g_w1T);
    cudaGetSymbolAddress((void**)&w2T,    g_w2T);
    cudaGetSymbolAddress((void**)&bqkv,   g_bqkv);

    cudaFuncSetAttribute(flash_attn, cudaFuncAttributeMaxDynamicSharedMemorySize, FA_SMEM_B);
    cudaFuncSetAttribute(gemm_mma<0>, cudaFuncAttributeMaxDynamicSharedMemorySize, GEMM_SMEM);
    cudaFuncSetAttribute(gemm_mma<1>, cudaFuncAttributeMaxDynamicSharedMemorySize, GEMM_SMEM);
    cudaFuncSetAttribute(gemm_mma<2>, cudaFuncAttributeMaxDynamicSharedMemorySize, GEMM_SMEM);

    dim3 tb(32, 8);
    batched_transpose<<<dim3(HS/32, DIM/32, NH), tb>>>(Wq, wqkvT,              DIM, HS);
    batched_transpose<<<dim3(HS/32, DIM/32, NH), tb>>>(Wk, wqkvT + DIM*DIM,    DIM, HS);
    batched_transpose<<<dim3(HS/32, DIM/32, NH), tb>>>(Wv, wqkvT + 2*DIM*DIM,  DIM, HS);
    batched_transpose<<<dim3(DIM/32, DIM/32, 1), tb>>>(Wproj, wprojT, DIM, DIM);
    batched_transpose<<<dim3(FFD/32, DIM/32, 1), tb>>>(W1, w1T, DIM, FFD);
    batched_transpose<<<dim3(DIM/32, FFD/32, 1), tb>>>(W2, w2T, FFD, DIM);
    pack_bias<<<(DIM + 255) / 256, 256>>>(bq, bk, bv);

    // 1. LN1
    ln_kernel<<<TOK, 256>>>(x, ln1_g, ln1_b, h);
    // 2. QKV
    gemm_mma<0><<<dim3(D3/256, TOK/128), 256, GEMM_SMEM>>>(h, wqkvT, bqkv, nullptr, qkv, TOK, D3, DIM);
    // 3. attention
    flash_attn<<<dim3(SEQ/128, BATCH*NH), 256, FA_SMEM_B>>>(qkv, attn);
    // 4. proj + residual(x)
    gemm_mma<1><<<dim3(DIM/256, TOK/128), 256, GEMM_SMEM>>>(attn, wprojT, bproj, x, x1, TOK, DIM, DIM);
    // 5. LN2
    ln_kernel<<<TOK, 256>>>(x1, ln2_g, ln2_b, h);
    // 6. FF1 + LeakyReLU
    gemm_mma<2><<<dim3(FFD/256, TOK/128), 256, GEMM_SMEM>>>(h, w1T, b1, nullptr, ff, TOK, FFD, DIM);
    // 7. FF2 + residual(x1) -> out
    gemm_mma<1><<<dim3(DIM/256, TOK/128), 256, GEMM_SMEM>>>(ff, w2T, b2, x1, out, TOK, DIM, FFD);
}

// round 6
// speedup vs baseline: 4.8016x; 1.9424x over previous
#include <cuda_runtime.h>
#include <math.h>
#include <cstdint>

#define BATCH 8
#define SEQ 1024
#define DIM 1024
#define NH 16
#define HS 64
#define TOK (BATCH*SEQ)   // 8192
#define FFD (4*DIM)       // 4096
#define D3  (3*DIM)       // 3072

// ---------------- scratch (device globals) ---------------------------------
__device__ float g_h[TOK*DIM];
__device__ float g_qkv[TOK*D3];
__device__ float g_attn[TOK*DIM];
__device__ float g_x1[TOK*DIM];
__device__ float g_ff[(size_t)TOK*FFD];
__device__ float g_wqkvT[D3*DIM];
__device__ float g_bqkv[D3];
__device__ float g_wprojT[DIM*DIM];
__device__ float g_w1T[FFD*DIM];
__device__ float g_w2T[DIM*FFD];

// ======================= helpers ===========================================
__device__ __forceinline__ uint32_t smem_u32(const void* p) {
    uint32_t a;
    asm("{ .reg .u64 t; cvta.to.shared.u64 t, %1; cvt.u32.u64 %0, t; }" : "=r"(a) : "l"(p));
    return a;
}
__device__ __forceinline__ void cpa16(uint32_t dst, const void* src) {
    asm volatile("cp.async.cg.shared.global [%0], [%1], 16;\n" :: "r"(dst), "l"(src));
}
__device__ __forceinline__ void cp_commit() {
    asm volatile("cp.async.commit_group;" ::: "memory");
}
template<int N>
__device__ __forceinline__ void cp_wait() {
    asm volatile("cp.async.wait_group %0;" :: "n"(N) : "memory");
}
__device__ __forceinline__ void mma_tf32(float* c, const uint32_t* a, const uint32_t* b) {
    asm volatile(
        "mma.sync.aligned.m16n8k8.row.col.f32.tf32.tf32.f32 "
        "{%0,%1,%2,%3}, {%4,%5,%6,%7}, {%8,%9}, {%0,%1,%2,%3};"
        : "+f"(c[0]), "+f"(c[1]), "+f"(c[2]), "+f"(c[3])
        : "r"(a[0]), "r"(a[1]), "r"(a[2]), "r"(a[3]), "r"(b[0]), "r"(b[1]));
}
// round-to-nearest tf32 (unbiased; removes truncation bias in mma operands)
__device__ __forceinline__ float tf32r(float x) {
    uint32_t u;
    asm("cvt.rna.tf32.f32 %0, %1;" : "=r"(u) : "f"(x));
    return __uint_as_float(u);
}

// ======================= weight transpose (+tf32 round) ====================
__global__ void batched_transpose(const float* __restrict__ in, float* __restrict__ out,
                                  int R, int C) {
    __shared__ float t[32][33];
    int z = blockIdx.z;
    const float* iz = in + (size_t)z * R * C;
    float* oz = out + (size_t)z * R * C;
    int bx = blockIdx.x * 32;
    int by = blockIdx.y * 32;
    int x = bx + threadIdx.x;
    #pragma unroll
    for (int i = threadIdx.y; i < 32; i += 8)
        t[i][threadIdx.x] = iz[(size_t)(by + i) * C + x];
    __syncthreads();
    int ox = by + threadIdx.x;
    #pragma unroll
    for (int i = threadIdx.y; i < 32; i += 8)
        oz[(size_t)(bx + i) * R + ox] = tf32r(t[threadIdx.x][i]);
}

__global__ void pack_bias(const float* __restrict__ bq, const float* __restrict__ bk,
                          const float* __restrict__ bv) {
    int i = blockIdx.x * blockDim.x + threadIdx.x;
    if (i < DIM) {
        g_bqkv[i]         = bq[i];
        g_bqkv[i + DIM]   = bk[i];
        g_bqkv[i + 2*DIM] = bv[i];
    }
}

// ---------------- layernorm (+tf32 round: output only feeds GEMMs) ---------
__global__ void ln_kernel(const float* __restrict__ x, const float* __restrict__ g,
                          const float* __restrict__ b, float* __restrict__ out) {
    int row = blockIdx.x;
    const float4* xr = (const float4*)(x + (size_t)row * DIM);
    float4 v = xr[threadIdx.x];
    float s  = v.x + v.y + v.z + v.w;
    float ss = v.x*v.x + v.y*v.y + v.z*v.z + v.w*v.w;
    #pragma unroll
    for (int o = 16; o; o >>= 1) {
        s  += __shfl_xor_sync(0xFFFFFFFFu, s, o);
        ss += __shfl_xor_sync(0xFFFFFFFFu, ss, o);
    }
    __shared__ float sm[8], sm2[8];
    int w = threadIdx.x >> 5, l = threadIdx.x & 31;
    if (l == 0) { sm[w] = s; sm2[w] = ss; }
    __syncthreads();
    if (w == 0) {
        s  = (l < 8) ? sm[l]  : 0.f;
        ss = (l < 8) ? sm2[l] : 0.f;
        #pragma unroll
        for (int o = 4; o; o >>= 1) {
            s  += __shfl_xor_sync(0xFFFFFFFFu, s, o);
            ss += __shfl_xor_sync(0xFFFFFFFFu, ss, o);
        }
        if (l == 0) { sm[0] = s; sm2[0] = ss; }
    }
    __syncthreads();
    float mu   = sm[0] * (1.0f / DIM);
    float var  = sm2[0] * (1.0f / DIM) - mu * mu;
    float rstd = rsqrtf(var + 1e-5f);
    float4 gg = ((const float4*)g)[threadIdx.x];
    float4 bb = ((const float4*)b)[threadIdx.x];
    float4 o4;
    o4.x = tf32r((v.x - mu) * rstd * gg.x + bb.x);
    o4.y = tf32r((v.y - mu) * rstd * gg.y + bb.y);
    o4.z = tf32r((v.z - mu) * rstd * gg.z + bb.z);
    o4.w = tf32r((v.w - mu) * rstd * gg.w + bb.w);
    ((float4*)(out + (size_t)row * DIM))[threadIdx.x] = o4;
}

// ======================= tf32 mma.sync GEMM (4-stage, 1 barrier) ===========
#define KC 32
#define ASTRIDE 36
#define A_ST_F (128 * ASTRIDE)
#define B_ST_F (256 * ASTRIDE)
#define STG_F (A_ST_F + B_ST_F)              // 13824 floats
#define GSTAGES 4
#define GEMM_SMEM (GSTAGES * STG_F * 4)      // 221184 bytes

__device__ __forceinline__ void load_chunk(int tid, uint32_t as, uint32_t bs,
                                           const float* Aj, const float* Bj, int K) {
    #pragma unroll
    for (int t = 0; t < 4; t++) {
        int v = tid + t * 256;
        int row = v >> 3, seg = v & 7;
        cpa16(as + (row * ASTRIDE + seg * 4) * 4, Aj + (size_t)row * K + seg * 4);
    }
    #pragma unroll
    for (int t = 0; t < 8; t++) {
        int v = tid + t * 256;
        int row = v >> 3, seg = v & 7;
        cpa16(bs + (row * ASTRIDE + seg * 4) * 4, Bj + (size_t)row * K + seg * 4);
    }
}

template<int EPI>   // 0 = bias(+rnd), 1 = bias+res, 2 = bias+leaky(+rnd)
__global__ __launch_bounds__(256, 1)
void gemm_mma(const float* __restrict__ A, const float* __restrict__ Bt,
              const float* __restrict__ bias, const float* __restrict__ res,
              float* __restrict__ C, int M, int N, int K) {
    extern __shared__ float smem[];
    uint32_t sb = smem_u32(smem);
    int tid = threadIdx.x;
    int wid = tid >> 5, lane = tid & 31;
    int grp = lane >> 2, tig = lane & 3;
    int wm = wid & 1, wn = wid >> 1;
    int bn = blockIdx.x, bm = blockIdx.y;
    int nch = K >> 5;

    const float* Ag = A + (size_t)bm * 128 * K;
    const float* Bg = Bt + (size_t)bn * 256 * K;

    #pragma unroll
    for (int j = 0; j < GSTAGES - 1; j++) {
        uint32_t st = sb + j * (STG_F * 4);
        load_chunk(tid, st, st + A_ST_F * 4, Ag + j * KC, Bg + j * KC, K);
        cp_commit();
    }

    float acc[4][8][4];
    #pragma unroll
    for (int i = 0; i < 4; i++)
        #pragma unroll
        for (int j = 0; j < 8; j++)
            #pragma unroll
            for (int q = 0; q < 4; q++) acc[i][j][q] = 0.f;

    for (int ch = 0; ch < nch; ch++) {
        int s = ch & 3;
        const float* As = smem + s * STG_F;
        const float* Bs = As + A_ST_F;
        cp_wait<2>();
        __syncthreads();
        if (ch + 3 < nch) {
            int sw = (ch + 3) & 3;
            uint32_t st = sb + sw * (STG_F * 4);
            load_chunk(tid, st, st + A_ST_F * 4,
                       Ag + (ch + 3) * KC, Bg + (ch + 3) * KC, K);
        }
        cp_commit();
        #pragma unroll
        for (int kk = 0; kk < 4; kk++) {
            int k = kk * 8;
            uint32_t a[4][4], b[8][2];
            #pragma unroll
            for (int i = 0; i < 4; i++) {
                const float* ar = As + (wm * 64 + i * 16 + grp) * ASTRIDE + k + tig;
                a[i][0] = __float_as_uint(ar[0]);
                a[i][2] = __float_as_uint(ar[4]);
                a[i][1] = __float_as_uint(ar[8 * ASTRIDE]);
                a[i][3] = __float_as_uint(ar[8 * ASTRIDE + 4]);
            }
            #pragma unroll
            for (int j = 0; j < 8; j++) {
                const float* br = Bs + (wn * 64 + j * 8 + grp) * ASTRIDE + k + tig;
                b[j][0] = __float_as_uint(br[0]);
                b[j][1] = __float_as_uint(br[4]);
            }
            #pragma unroll
            for (int i = 0; i < 4; i++)
                #pragma unroll
                for (int j = 0; j < 8; j++)
                    mma_tf32(acc[i][j], a[i], b[j]);
        }
    }

    #pragma unroll
    for (int i = 0; i < 4; i++) {
        int row0 = bm * 128 + wm * 64 + i * 16 + grp;
        #pragma unroll
        for (int j = 0; j < 8; j++) {
            int col = bn * 256 + wn * 64 + j * 8 + tig * 2;
            float b0 = bias[col], b1 = bias[col + 1];
            #pragma unroll
            for (int half = 0; half < 2; half++) {
                int row = row0 + half * 8;
                float v0 = acc[i][j][2 * half]     + b0;
                float v1 = acc[i][j][2 * half + 1] + b1;
                if (EPI == 2) {
                    v0 = v0 > 0.f ? v0 : 0.01f * v0;
                    v1 = v1 > 0.f ? v1 : 0.01f * v1;
                }
                if (EPI == 1) {
                    float2 rv = *(const float2*)(res + (size_t)row * N + col);
                    v0 += rv.x; v1 += rv.y;
                } else {
                    v0 = tf32r(v0); v1 = tf32r(v1);   // output feeds a GEMM/MMA
                }
                float2 w2; w2.x = v0; w2.y = v1;
                *(float2*)(C + (size_t)row * N + col) = w2;
            }
        }
    }
}

// ======================= tensor-core flash attention =======================
// q-tile 128 (8 warps x 16 rows), key-tile 64, tf32 mma.sync.
#define PST 68
#define FA_SMEM_B (512 * PST * 4)   // Qs 128 + Ks 2*64 + Vt 2*64 + Ps 128 rows

__global__ __launch_bounds__(256)
void flash_attn_mma(const float* __restrict__ qkv, float* __restrict__ attn_out) {
    extern __shared__ float fs[];
    float* Qs = fs;                    // [128][PST]
    float* Ks = fs + 128 * PST;        // [2][64][PST]  (B for QK: [key][d])
    float* Vt = fs + 256 * PST;        // [2][64][PST]  (B for PV: [d][key])
    float* Ps = fs + 384 * PST;        // [128][PST]    (A for PV: [q][key])
    uint32_t sb = smem_u32(fs);

    int tid = threadIdx.x;
    int wid = tid >> 5, lane = tid & 31;
    int grp = lane >> 2, tig = lane & 3;
    int bh = blockIdx.y;
    int b = bh >> 4, h = bh & 15;
    int q0 = blockIdx.x * 128;

    const float* qb = qkv + (size_t)(b * SEQ + q0) * D3 + h * HS;
    const float* kb = qkv + (size_t)(b * SEQ) * D3 + DIM + h * HS;
    const float* vb = kb + DIM;

    // Q tile: 128 rows x 16 segments of 16B  (2048 copies, 8 per thread)
    #pragma unroll
    for (int t = 0; t < 8; t++) {
        int v = tid + t * 256;
        int row = v >> 4, seg = v & 15;
        cpa16(sb + (row * PST + seg * 4) * 4, qb + (size_t)row * D3 + seg * 4);
    }
    // K tile 0: 64 rows x 16 segments (1024 copies, 4 per thread)
    #pragma unroll
    for (int t = 0; t < 4; t++) {
        int v = tid + t * 256;
        int row = v >> 4, seg = v & 15;
        cpa16(sb + (128 * PST + row * PST + seg * 4) * 4, kb + (size_t)row * D3 + seg * 4);
    }
    cp_commit();

    // V tile 0 into regs (transposed store later)
    int kr = lane + 32 * (wid & 1);      // key row 0..63
    int dsg = wid >> 1;                  // d segment: d = 16*dsg + i
    float4 vv[4];
    #pragma unroll
    for (int i = 0; i < 4; i++)
        vv[i] = *(const float4*)(vb + (size_t)kr * D3 + dsg * 16 + i * 4);

    cp_wait<0>();
    __syncthreads();
    #pragma unroll
    for (int i = 0; i < 4; i++) {
        float fv[4] = {vv[i].x, vv[i].y, vv[i].z, vv[i].w};
        #pragma unroll
        for (int q = 0; q < 4; q++)
            Vt[(dsg * 16 + i * 4 + q) * PST + kr] = fv[q];
    }
    __syncthreads();

    float o[8][4];
    #pragma unroll
    for (int j = 0; j < 8; j++)
        #pragma unroll
        for (int q = 0; q < 4; q++) o[j][q] = 0.f;
    float m0 = -1e30f, m1 = -1e30f, l0 = 0.f, l1 = 0.f;

    const int NT = SEQ / 64;
    for (int kt = 0; kt < NT; kt++) {
        int pb = kt & 1, nb = pb ^ 1;
        float* Kc = Ks + pb * 64 * PST;
        float* Vc = Vt + pb * 64 * PST;

        if (kt + 1 < NT) {
            #pragma unroll
            for (int t = 0; t < 4; t++) {
                int v = tid + t * 256;
                int row = v >> 4, seg = v & 15;
                cpa16(sb + (128 * PST + (nb * 64 + row) * PST + seg * 4) * 4,
                      kb + (size_t)((kt + 1) * 64 + row) * D3 + seg * 4);
            }
            cp_commit();
            #pragma unroll
            for (int i = 0; i < 4; i++)
                vv[i] = *(const float4*)(vb + (size_t)((kt + 1) * 64 + kr) * D3 + dsg * 16 + i * 4);
        }

        // ---- S = Q K^T ----
        float s[8][4];
        #pragma unroll
        for (int j = 0; j < 8; j++)
            #pragma unroll
            for (int q = 0; q < 4; q++) s[j][q] = 0.f;
        #pragma unroll
        for (int ks = 0; ks < 8; ks++) {
            int k = ks * 8;
            uint32_t a[4], bfr[8][2];
            const float* ar = Qs + (wid * 16 + grp) * PST + k + tig;
            a[0] = __float_as_uint(ar[0]);
            a[1] = __float_as_uint(ar[8 * PST]);
            a[2] = __float_as_uint(ar[4]);
            a[3] = __float_as_uint(ar[8 * PST + 4]);
            #pragma unroll
            for (int j = 0; j < 8; j++) {
                const float* br = Kc + (j * 8 + grp) * PST + k + tig;
                bfr[j][0] = __float_as_uint(br[0]);
                bfr[j][1] = __float_as_uint(br[4]);
            }
            #pragma unroll
            for (int j = 0; j < 8; j++) mma_tf32(s[j], a, bfr[j]);
        }

        // ---- online softmax ----
        float mt0 = -1e30f, mt1 = -1e30f;
        #pragma unroll
        for (int j = 0; j < 8; j++) {
            s[j][0] *= 0.125f; s[j][1] *= 0.125f; s[j][2] *= 0.125f; s[j][3] *= 0.125f;
            mt0 = fmaxf(mt0, fmaxf(s[j][0], s[j][1]));
            mt1 = fmaxf(mt1, fmaxf(s[j][2], s[j][3]));
        }
        mt0 = fmaxf(mt0, __shfl_xor_sync(0xFFFFFFFFu, mt0, 1));
        mt0 = fmaxf(mt0, __shfl_xor_sync(0xFFFFFFFFu, mt0, 2));
        mt1 = fmaxf(mt1, __shfl_xor_sync(0xFFFFFFFFu, mt1, 1));
        mt1 = fmaxf(mt1, __shfl_xor_sync(0xFFFFFFFFu, mt1, 2));
        float mn0 = fmaxf(m0, mt0), mn1 = fmaxf(m1, mt1);
        float al0 = __expf(m0 - mn0), al1 = __expf(m1 - mn1);
        float lt0 = 0.f, lt1 = 0.f;
        #pragma unroll
        for (int j = 0; j < 8; j++) {
            s[j][0] = __expf(s[j][0] - mn0); s[j][1] = __expf(s[j][1] - mn0);
            s[j][2] = __expf(s[j][2] - mn1); s[j][3] = __expf(s[j][3] - mn1);
            lt0 += s[j][0] + s[j][1];
            lt1 += s[j][2] + s[j][3];
        }
        lt0 += __shfl_xor_sync(0xFFFFFFFFu, lt0, 1);
        lt0 += __shfl_xor_sync(0xFFFFFFFFu, lt0, 2);
        lt1 += __shfl_xor_sync(0xFFFFFFFFu, lt1, 1);
        lt1 += __shfl_xor_sync(0xFFFFFFFFu, lt1, 2);
        m0 = mn0; m1 = mn1;
        l0 = l0 * al0 + lt0;
        l1 = l1 * al1 + lt1;
        #pragma unroll
        for (int j = 0; j < 8; j++) {
            o[j][0] *= al0; o[j][1] *= al0; o[j][2] *= al1; o[j][3] *= al1;
        }
        // store P (tf32-rounded) for the PV mma
        #pragma unroll
        for (int j = 0; j < 8; j++) {
            float2 p01; p01.x = tf32r(s[j][0]); p01.y = tf32r(s[j][1]);
            float2 p23; p23.x = tf32r(s[j][2]); p23.y = tf32r(s[j][3]);
            *(float2*)(Ps + (wid * 16 + grp) * PST + j * 8 + tig * 2) = p01;
            *(float2*)(Ps + (wid * 16 + grp + 8) * PST + j * 8 + tig * 2) = p23;
        }
        __syncwarp();

        // ---- O += P V ----
        #pragma unroll
        for (int ks = 0; ks < 8; ks++) {
            int k = ks * 8;
            uint32_t a[4], bfr[8][2];
            const float* ar = Ps + (wid * 16 + grp) * PST + k + tig;
            a[0] = __float_as_uint(ar[0]);
            a[1] = __float_as_uint(ar[8 * PST]);
            a[2] = __float_as_uint(ar[4]);
            a[3] = __float_as_uint(ar[8 * PST + 4]);
            #pragma unroll
            for (int j = 0; j < 8; j++) {
                const float* br = Vc + (j * 8 + grp) * PST + k + tig;
                bfr[j][0] = __float_as_uint(br[0]);
                bfr[j][1] = __float_as_uint(br[4]);
            }
            #pragma unroll
            for (int j = 0; j < 8; j++) mma_tf32(o[j], a, bfr[j]);
        }

        if (kt + 1 < NT) {
            cp_wait<0>();
            __syncthreads();
            float* Vn = Vt + nb * 64 * PST;
            #pragma unroll
            for (int i = 0; i < 4; i++) {
                float fv[4] = {vv[i].x, vv[i].y, vv[i].z, vv[i].w};
                #pragma unroll
                for (int q = 0; q < 4; q++)
                    Vn[(dsg * 16 + i * 4 + q) * PST + kr] = fv[q];
            }
            __syncthreads();
        }
    }

    // ---- epilogue (tf32-rounded: feeds proj GEMM) ----
    float inv0 = 1.0f / l0, inv1 = 1.0f / l1;
    size_t r0 = (size_t)(b * SEQ + q0 + wid * 16 + grp);
    #pragma unroll
    for (int j = 0; j < 8; j++) {
        int col = h * HS + j * 8 + tig * 2;
        float2 w0; w0.x = tf32r(o[j][0] * inv0); w0.y = tf32r(o[j][1] * inv0);
        float2 w1; w1.x = tf32r(o[j][2] * inv1); w1.y = tf32r(o[j][3] * inv1);
        *(float2*)(attn_out + r0 * DIM + col) = w0;
        *(float2*)(attn_out + (r0 + 8) * DIM + col) = w1;
    }
}

// ---------------- host orchestration ---------------------------------------
extern "C" void kernel_launch(void* const* d_in, const int* in_sizes, int n_in,
                              void* d_out, int out_size) {
    const float* x     = (const float*)d_in[0];
    const float* Wq    = (const float*)d_in[1];
    const float* bq    = (const float*)d_in[2];
    const float* Wk    = (const float*)d_in[3];
    const float* bk    = (const float*)d_in[4];
    const float* Wv    = (const float*)d_in[5];
    const float* bv    = (const float*)d_in[6];
    const float* Wproj = (const float*)d_in[7];
    const float* bproj = (const float*)d_in[8];
    const float* W1    = (const float*)d_in[9];
    const float* b1    = (const float*)d_in[10];
    const float* W2    = (const float*)d_in[11];
    const float* b2    = (const float*)d_in[12];
    const float* ln1_g = (const float*)d_in[13];
    const float* ln1_b = (const float*)d_in[14];
    const float* ln2_g = (const float*)d_in[15];
    const float* ln2_b = (const float*)d_in[16];
    float* out = (float*)d_out;

    float *h, *qkv, *attn, *x1, *ff, *wqkvT, *wprojT, *w1T, *w2T, *bqkv;
    cudaGetSymbolAddress((void**)&h,      g_h);
    cudaGetSymbolAddress((void**)&qkv,    g_qkv);
    cudaGetSymbolAddress((void**)&attn,   g_attn);
    cudaGetSymbolAddress((void**)&x1,     g_x1);
    cudaGetSymbolAddress((void**)&ff,     g_ff);
    cudaGetSymbolAddress((void**)&wqkvT,  g_wqkvT);
    cudaGetSymbolAddress((void**)&wprojT, g_wprojT);
    cudaGetSymbolAddress((void**)&w1T,    g_w1T);
    cudaGetSymbolAddress((void**)&w2T,    g_w2T);
    cudaGetSymbolAddress((void**)&bqkv,   g_bqkv);

    cudaFuncSetAttribute(flash_attn_mma, cudaFuncAttributeMaxDynamicSharedMemorySize, FA_SMEM_B);
    cudaFuncSetAttribute(gemm_mma<0>, cudaFuncAttributeMaxDynamicSharedMemorySize, GEMM_SMEM);
    cudaFuncSetAttribute(gemm_mma<1>, cudaFuncAttributeMaxDynamicSharedMemorySize, GEMM_SMEM);
    cudaFuncSetAttribute(gemm_mma<2>, cudaFuncAttributeMaxDynamicSharedMemorySize, GEMM_SMEM);

    dim3 tb(32, 8);
    batched_transpose<<<dim3(HS/32, DIM/32, NH), tb>>>(Wq, wqkvT,              DIM, HS);
    batched_transpose<<<dim3(HS/32, DIM/32, NH), tb>>>(Wk, wqkvT + DIM*DIM,    DIM, HS);
    batched_transpose<<<dim3(HS/32, DIM/32, NH), tb>>>(Wv, wqkvT + 2*DIM*DIM,  DIM, HS);
    batched_transpose<<<dim3(DIM/32, DIM/32, 1), tb>>>(Wproj, wprojT, DIM, DIM);
    batched_transpose<<<dim3(FFD/32, DIM/32, 1), tb>>>(W1, w1T, DIM, FFD);
    batched_transpose<<<dim3(DIM/32, FFD/32, 1), tb>>>(W2, w2T, FFD, DIM);
    pack_bias<<<(DIM + 255) / 256, 256>>>(bq, bk, bv);

    ln_kernel<<<TOK, 256>>>(x, ln1_g, ln1_b, h);
    gemm_mma<0><<<dim3(D3/256, TOK/128), 256, GEMM_SMEM>>>(h, wqkvT, bqkv, nullptr, qkv, TOK, D3, DIM);
    flash_attn_mma<<<dim3(SEQ/128, BATCH*NH), 256, FA_SMEM_B>>>(qkv, attn);
    gemm_mma<1><<<dim3(DIM/256, TOK/128), 256, GEMM_SMEM>>>(attn, wprojT, bproj, x, x1, TOK, DIM, DIM);
    ln_kernel<<<TOK, 256>>>(x1, ln2_g, ln2_b, h);
    gemm_mma<2><<<dim3(FFD/256, TOK/128), 256, GEMM_SMEM>>>(h, w1T, b1, nullptr, ff, TOK, FFD, DIM);
    gemm_mma<1><<<dim3(DIM/256, TOK/128), 256, GEMM_SMEM>>>(ff, w2T, b2, x1, out, TOK, DIM, FFD);
}